// round 4
// baseline (speedup 1.0000x reference)
#include <cuda_runtime.h>

#define B_ 4096
#define N_ 64
#define H_ 256
#define TB3 16

#define NB_GEMM 320
#define NB_UV   2048
#define NB_K3   1024

typedef unsigned long long u64;

// Scratch (allocation-free rule: __device__ globals)
__device__ float g_UV[N_ * H_];     //  64 KiB
__device__ float g_sW[B_ * H_];     //   4 MiB
__device__ float g_gate[B_ * N_];   //   1 MiB
__device__ int g_flag_w[64];        // per 64-b tile: 5 producer blocks each
__device__ int g_flag_uv;           // 2048 UV blocks

// ---------- packed fp32x2 helpers (sm_103a FFMA2) ----------
__device__ __forceinline__ u64 fma2(u64 a, u64 b, u64 c) {
    u64 d; asm("fma.rn.f32x2 %0, %1, %2, %3;" : "=l"(d) : "l"(a), "l"(b), "l"(c)); return d;
}
__device__ __forceinline__ float2 unpack2(u64 v) {
    float2 r; asm("mov.b64 {%0, %1}, %2;" : "=f"(r.x), "=f"(r.y) : "l"(v)); return r;
}

__global__ void k_reset() {
    const int t = threadIdx.x;
    if (t < 64) g_flag_w[t] = 0;
    if (t == 64) g_flag_uv = 0;
}

__device__ __forceinline__ void row_step(const float4 uv, const float4 hh,
                                         const float4 sw, const float g,
                                         const float a, float4& o, float& ss)
{
    float c, t;
    c = uv.x + sw.x; c = (c >= 0.f) ? c : a * c; t = fmaf(g, c, hh.x); o.x = t; ss = fmaf(t, t, ss);
    c = uv.y + sw.y; c = (c >= 0.f) ? c : a * c; t = fmaf(g, c, hh.y); o.y = t; ss = fmaf(t, t, ss);
    c = uv.z + sw.z; c = (c >= 0.f) ? c : a * c; t = fmaf(g, c, hh.z); o.z = t; ss = fmaf(t, t, ss);
    c = uv.w + sw.w; c = (c >= 0.f) ? c : a * c; t = fmaf(g, c, hh.w); o.w = t; ss = fmaf(t, t, ss);
}

// ---------------------------------------------------------------------------
// Mega kernel, one launch, three roles by blockIdx.x:
//  [0, 320):          GEMM  C[b,m] = s_t[b,:].M[m,:], M = concat(W_w, h+w)
//                     64x64 tile, Kc=32, dup-A smem, f32x2 FMA.  Sets g_flag_w.
//  [320, 2368):       UV[n,k] = sum_h h.U + w.V (warp per element). g_flag_uv.
//  [2368, 3392):      k3: out = normalize(h + gate*prelu(UV + sW)); spins on
//                     flags for its b-tile, then R2-style streaming loop.
// ---------------------------------------------------------------------------
__global__ void __launch_bounds__(256) mega(
    const float* __restrict__ s, const float* __restrict__ W,
    const float* __restrict__ h, const float* __restrict__ w,
    const float* __restrict__ U, const float* __restrict__ V,
    const float* __restrict__ a_ptr, float* __restrict__ out)
{
    __shared__ union {
        struct { float sa_dup[32][128]; float sb[32][64]; } g;   // 24 KiB
        struct { float4 sw[2][64]; float gt[2][16]; } c;
    } sm;

    const int tid = threadIdx.x;
    const int blk = blockIdx.x;

    if (blk < NB_GEMM) {
        // ================= GEMM =================
        const int mx = blk % 5;
        const int b0 = (blk / 5) * 64;
        const int m0 = mx * 64;
        const bool gate_tile = (mx == 4);

        const int row = tid & 63;
        const int kq = (tid >> 6) << 2;    // 0,4,8,12
        const int tx = tid & 15;
        const int ty = tid >> 4;
        const int rb = ty << 2;            // b micro row base
        const int cm = tx << 2;            // m micro col base

        u64 acc2[4][2] = {};

        float4 ra0, ra1, rb0, rb1;
        ra0 = *(const float4*)&s[(b0 + row) * H_ + kq];
        ra1 = *(const float4*)&s[(b0 + row) * H_ + 16 + kq];
        if (!gate_tile) {
            rb0 = *(const float4*)&W[(m0 + row) * H_ + kq];
            rb1 = *(const float4*)&W[(m0 + row) * H_ + 16 + kq];
        } else {
            float4 x0 = *(const float4*)&h[row * H_ + kq];
            float4 x1 = *(const float4*)&h[row * H_ + 16 + kq];
            float4 y0 = *(const float4*)&w[row * H_ + kq];
            float4 y1 = *(const float4*)&w[row * H_ + 16 + kq];
            rb0 = make_float4(x0.x + y0.x, x0.y + y0.y, x0.z + y0.z, x0.w + y0.w);
            rb1 = make_float4(x1.x + y1.x, x1.y + y1.y, x1.z + y1.z, x1.w + y1.w);
        }

        for (int kc = 0; kc < H_; kc += 32) {
            // stage: A duplicated pairs (k-major), B natural (k-major)
            *(float2*)&sm.g.sa_dup[kq + 0][2 * row] = make_float2(ra0.x, ra0.x);
            *(float2*)&sm.g.sa_dup[kq + 1][2 * row] = make_float2(ra0.y, ra0.y);
            *(float2*)&sm.g.sa_dup[kq + 2][2 * row] = make_float2(ra0.z, ra0.z);
            *(float2*)&sm.g.sa_dup[kq + 3][2 * row] = make_float2(ra0.w, ra0.w);
            *(float2*)&sm.g.sa_dup[16 + kq + 0][2 * row] = make_float2(ra1.x, ra1.x);
            *(float2*)&sm.g.sa_dup[16 + kq + 1][2 * row] = make_float2(ra1.y, ra1.y);
            *(float2*)&sm.g.sa_dup[16 + kq + 2][2 * row] = make_float2(ra1.z, ra1.z);
            *(float2*)&sm.g.sa_dup[16 + kq + 3][2 * row] = make_float2(ra1.w, ra1.w);
            sm.g.sb[kq + 0][row] = rb0.x; sm.g.sb[kq + 1][row] = rb0.y;
            sm.g.sb[kq + 2][row] = rb0.z; sm.g.sb[kq + 3][row] = rb0.w;
            sm.g.sb[16 + kq + 0][row] = rb1.x; sm.g.sb[16 + kq + 1][row] = rb1.y;
            sm.g.sb[16 + kq + 2][row] = rb1.z; sm.g.sb[16 + kq + 3][row] = rb1.w;
            __syncthreads();

            if (kc + 32 < H_) {
                const int kn = kc + 32;
                ra0 = *(const float4*)&s[(b0 + row) * H_ + kn + kq];
                ra1 = *(const float4*)&s[(b0 + row) * H_ + kn + 16 + kq];
                if (!gate_tile) {
                    rb0 = *(const float4*)&W[(m0 + row) * H_ + kn + kq];
                    rb1 = *(const float4*)&W[(m0 + row) * H_ + kn + 16 + kq];
                } else {
                    float4 x0 = *(const float4*)&h[row * H_ + kn + kq];
                    float4 x1 = *(const float4*)&h[row * H_ + kn + 16 + kq];
                    float4 y0 = *(const float4*)&w[row * H_ + kn + kq];
                    float4 y1 = *(const float4*)&w[row * H_ + kn + 16 + kq];
                    rb0 = make_float4(x0.x + y0.x, x0.y + y0.y, x0.z + y0.z, x0.w + y0.w);
                    rb1 = make_float4(x1.x + y1.x, x1.y + y1.y, x1.z + y1.z, x1.w + y1.w);
                }
            }

#pragma unroll 8
            for (int k = 0; k < 32; ++k) {
                const ulonglong2 ad01 = *(const ulonglong2*)&sm.g.sa_dup[k][2 * rb];
                const ulonglong2 ad23 = *(const ulonglong2*)&sm.g.sa_dup[k][2 * rb + 4];
                const ulonglong2 bp = *(const ulonglong2*)&sm.g.sb[k][cm];
                acc2[0][0] = fma2(ad01.x, bp.x, acc2[0][0]);
                acc2[0][1] = fma2(ad01.x, bp.y, acc2[0][1]);
                acc2[1][0] = fma2(ad01.y, bp.x, acc2[1][0]);
                acc2[1][1] = fma2(ad01.y, bp.y, acc2[1][1]);
                acc2[2][0] = fma2(ad23.x, bp.x, acc2[2][0]);
                acc2[2][1] = fma2(ad23.x, bp.y, acc2[2][1]);
                acc2[3][0] = fma2(ad23.y, bp.x, acc2[3][0]);
                acc2[3][1] = fma2(ad23.y, bp.y, acc2[3][1]);
            }
            __syncthreads();
        }

#pragma unroll
        for (int bi = 0; bi < 4; ++bi) {
            float2 p0 = unpack2(acc2[bi][0]);
            float2 p1 = unpack2(acc2[bi][1]);
            const int b = b0 + rb + bi;
            if (!gate_tile) {
                *(float4*)&g_sW[b * H_ + m0 + cm] = make_float4(p0.x, p0.y, p1.x, p1.y);
            } else {
                *(float4*)&g_gate[b * N_ + cm] = make_float4(
                    1.0f / (1.0f + __expf(-p0.x)), 1.0f / (1.0f + __expf(-p0.y)),
                    1.0f / (1.0f + __expf(-p1.x)), 1.0f / (1.0f + __expf(-p1.y)));
            }
        }
        __threadfence();
        __syncthreads();
        if (tid == 0) atomicAdd(&g_flag_w[blk / 5], 1);

    } else if (blk < NB_GEMM + NB_UV) {
        // ================= UV =================
        const int id = blk - NB_GEMM;
        const int n = id >> 5;
        const int kg = id & 31;
        const int warp = tid >> 5;
        const int lane = tid & 31;
        const int k = kg * 8 + warp;
        const int off = lane * 8;

        const float4* u4 = (const float4*)(U + k * H_ + off);
        const float4* v4 = (const float4*)(V + k * H_ + off);
        const float4* h4 = (const float4*)(h + n * H_ + off);
        const float4* w4 = (const float4*)(w + n * H_ + off);
        float4 u0 = u4[0], u1 = u4[1];
        float4 v0 = v4[0], v1 = v4[1];
        float4 x0 = __ldg(h4), x1 = __ldg(h4 + 1);
        float4 y0 = __ldg(w4), y1 = __ldg(w4 + 1);

        float acc = 0.f;
        acc = fmaf(u0.x, x0.x, acc); acc = fmaf(u0.y, x0.y, acc);
        acc = fmaf(u0.z, x0.z, acc); acc = fmaf(u0.w, x0.w, acc);
        acc = fmaf(u1.x, x1.x, acc); acc = fmaf(u1.y, x1.y, acc);
        acc = fmaf(u1.z, x1.z, acc); acc = fmaf(u1.w, x1.w, acc);
        acc = fmaf(v0.x, y0.x, acc); acc = fmaf(v0.y, y0.y, acc);
        acc = fmaf(v0.z, y0.z, acc); acc = fmaf(v0.w, y0.w, acc);
        acc = fmaf(v1.x, y1.x, acc); acc = fmaf(v1.y, y1.y, acc);
        acc = fmaf(v1.z, y1.z, acc); acc = fmaf(v1.w, y1.w, acc);

#pragma unroll
        for (int offm = 16; offm > 0; offm >>= 1)
            acc += __shfl_xor_sync(0xFFFFFFFFu, acc, offm);
        if (lane == 0) g_UV[n * H_ + k] = acc;

        __threadfence();
        __syncthreads();
        if (tid == 0) atomicAdd(&g_flag_uv, 1);

    } else {
        // ================= k3 (consumer) =================
        const int id = blk - (NB_GEMM + NB_UV);
        const int n0 = (id & 3) * 16;
        const int b0 = (id >> 2) * TB3;
        const int bt = b0 >> 6;

        if (tid == 0) {
            while (atomicAdd(&g_flag_w[bt], 0) < 5) __nanosleep(64);
            while (atomicAdd(&g_flag_uv, 0) < NB_UV) __nanosleep(64);
            __threadfence();
        }
        __syncthreads();

        const int warp = tid >> 5;
        const int lane = tid & 31;
        const float a = __ldg(a_ptr);

        const int nA = n0 + warp;
        const int nB = n0 + warp + 8;
        const int k0 = lane * 4;
        const int k1 = 128 + lane * 4;

        float4 uvA0 = *(const float4*)&g_UV[nA * H_ + k0];
        float4 uvA1 = *(const float4*)&g_UV[nA * H_ + k1];
        float4 uvB0 = *(const float4*)&g_UV[nB * H_ + k0];
        float4 uvB1 = *(const float4*)&g_UV[nB * H_ + k1];
        float4 hA0 = __ldg((const float4*)&h[nA * H_ + k0]);
        float4 hA1 = __ldg((const float4*)&h[nA * H_ + k1]);
        float4 hB0 = __ldg((const float4*)&h[nB * H_ + k0]);
        float4 hB1 = __ldg((const float4*)&h[nB * H_ + k1]);

        if (tid < 64) sm.c.sw[0][tid] = __ldg((const float4*)&g_sW[(size_t)b0 * H_] + tid);
        else if (tid < 80) sm.c.gt[0][tid - 64] = __ldg(&g_gate[b0 * N_ + n0 + (tid - 64)]);
        __syncthreads();

        for (int i = 0; i < TB3; ++i) {
            const int buf = i & 1;
            if (i + 1 < TB3) {
                const int bn = b0 + i + 1;
                if (tid < 64) sm.c.sw[buf ^ 1][tid] = __ldg((const float4*)&g_sW[(size_t)bn * H_] + tid);
                else if (tid < 80) sm.c.gt[buf ^ 1][tid - 64] = __ldg(&g_gate[bn * N_ + n0 + (tid - 64)]);
            }

            const float4 s0 = sm.c.sw[buf][lane];
            const float4 s1 = sm.c.sw[buf][lane + 32];
            const float gA = sm.c.gt[buf][warp];
            const float gB = sm.c.gt[buf][warp + 8];

            float4 oA0, oA1, oB0, oB1;
            float ssA = 0.f, ssB = 0.f;
            row_step(uvA0, hA0, s0, gA, a, oA0, ssA);
            row_step(uvA1, hA1, s1, gA, a, oA1, ssA);
            row_step(uvB0, hB0, s0, gB, a, oB0, ssB);
            row_step(uvB1, hB1, s1, gB, a, oB1, ssB);

#pragma unroll
            for (int offm = 16; offm > 0; offm >>= 1) {
                ssA += __shfl_xor_sync(0xFFFFFFFFu, ssA, offm);
                ssB += __shfl_xor_sync(0xFFFFFFFFu, ssB, offm);
            }
            const float iA = rsqrtf(ssA);
            const float iB = rsqrtf(ssB);

            const int b = b0 + i;
            float4* oA = (float4*)&out[((size_t)b * N_ + nA) * H_];
            float4* oB = (float4*)&out[((size_t)b * N_ + nB) * H_];
            oA[lane]      = make_float4(oA0.x * iA, oA0.y * iA, oA0.z * iA, oA0.w * iA);
            oA[32 + lane] = make_float4(oA1.x * iA, oA1.y * iA, oA1.z * iA, oA1.w * iA);
            oB[lane]      = make_float4(oB0.x * iB, oB0.y * iB, oB0.z * iB, oB0.w * iB);
            oB[32 + lane] = make_float4(oB1.x * iB, oB1.y * iB, oB1.z * iB, oB1.w * iB);

            __syncthreads();
        }
    }
}

// ---------------------------------------------------------------------------
extern "C" void kernel_launch(void* const* d_in, const int* in_sizes, int n_in,
                              void* d_out, int out_size)
{
    const float* s_t = (const float*)d_in[0];   // [B,H]
    const float* h   = (const float*)d_in[1];   // [1,N,H]
    const float* w   = (const float*)d_in[2];   // [1,N,H]
    const float* U   = (const float*)d_in[3];   // [H,H]
    const float* V   = (const float*)d_in[4];   // [H,H]
    const float* W   = (const float*)d_in[5];   // [H,H]
    const float* pa  = (const float*)d_in[6];   // [1]
    float* out = (float*)d_out;                 // [B,N,H]

    k_reset<<<1, 128>>>();
    mega<<<NB_GEMM + NB_UV + NB_K3, 256>>>(s_t, W, h, w, U, V, pa, out);
}

// round 5
// speedup vs baseline: 1.4315x; 1.4315x over previous
#include <cuda_runtime.h>

#define B_ 4096
#define N_ 64
#define H_ 256
#define TB3 16

typedef unsigned long long u64;

// Scratch (allocation-free rule: __device__ globals)
__device__ float g_UV[N_ * H_];     //  64 KiB
__device__ float g_sW[B_ * H_];     //   4 MiB
__device__ float g_gate[B_ * N_];   //   1 MiB

// ---------- packed fp32x2 helpers (sm_103a FFMA2) ----------
__device__ __forceinline__ u64 fma2(u64 a, u64 b, u64 c) {
    u64 d; asm("fma.rn.f32x2 %0, %1, %2, %3;" : "=l"(d) : "l"(a), "l"(b), "l"(c)); return d;
}
__device__ __forceinline__ float2 unpack2(u64 v) {
    float2 r; asm("mov.b64 {%0, %1}, %2;" : "=f"(r.x), "=f"(r.y) : "l"(v)); return r;
}

// ---------------------------------------------------------------------------
// Merged kernel 1+2:
//  blocks [0,320):    GEMM  C[b,m] = s_t[b,:] . M[m,:], M = concat(W_w, h+w)
//    64b x 64m tile, Kc=32, k-major smem with A stored as duplicated pairs
//    so FFMA2 operands load directly (3 LDS.128 + 8 FFMA2 per 16 MACs).
//    m<256 -> g_sW ; gate tile -> g_gate = sigmoid(C)
//  blocks [320,2368): UV[n,k] = sum_h h[n,h]*U[k,h] + w[n,h]*V[k,h]
// ---------------------------------------------------------------------------
__global__ void __launch_bounds__(256) k12(
    const float* __restrict__ s, const float* __restrict__ W,
    const float* __restrict__ h, const float* __restrict__ w,
    const float* __restrict__ U, const float* __restrict__ V)
{
    __shared__ float sa_dup[32][128];  // [k][2*b_local] duplicated pairs, 16 KiB
    __shared__ float sb[32][64];       // [k][m_local], 8 KiB

    const int tid = threadIdx.x;
    const int blk = blockIdx.x;

    if (blk < 320) {
        const int mx = blk % 5;
        const int b0 = (blk / 5) * 64;
        const int m0 = mx * 64;
        const bool gate_tile = (mx == 4);

        const int row = tid & 63;
        const int kq = (tid >> 6) << 2;    // 0,4,8,12
        const int tx = tid & 15;
        const int ty = tid >> 4;
        const int rb = ty << 2;            // b micro row base (4 rows)
        const int cm = tx << 2;            // m micro col base (4 cols)

        u64 acc2[4][2] = {};

        float4 ra0, ra1, rb0, rb1;
        ra0 = *(const float4*)&s[(b0 + row) * H_ + kq];
        ra1 = *(const float4*)&s[(b0 + row) * H_ + 16 + kq];
        if (!gate_tile) {
            rb0 = *(const float4*)&W[(m0 + row) * H_ + kq];
            rb1 = *(const float4*)&W[(m0 + row) * H_ + 16 + kq];
        } else {
            float4 x0 = *(const float4*)&h[row * H_ + kq];
            float4 x1 = *(const float4*)&h[row * H_ + 16 + kq];
            float4 y0 = *(const float4*)&w[row * H_ + kq];
            float4 y1 = *(const float4*)&w[row * H_ + 16 + kq];
            rb0 = make_float4(x0.x + y0.x, x0.y + y0.y, x0.z + y0.z, x0.w + y0.w);
            rb1 = make_float4(x1.x + y1.x, x1.y + y1.y, x1.z + y1.z, x1.w + y1.w);
        }

        for (int kc = 0; kc < H_; kc += 32) {
            *(float2*)&sa_dup[kq + 0][2 * row] = make_float2(ra0.x, ra0.x);
            *(float2*)&sa_dup[kq + 1][2 * row] = make_float2(ra0.y, ra0.y);
            *(float2*)&sa_dup[kq + 2][2 * row] = make_float2(ra0.z, ra0.z);
            *(float2*)&sa_dup[kq + 3][2 * row] = make_float2(ra0.w, ra0.w);
            *(float2*)&sa_dup[16 + kq + 0][2 * row] = make_float2(ra1.x, ra1.x);
            *(float2*)&sa_dup[16 + kq + 1][2 * row] = make_float2(ra1.y, ra1.y);
            *(float2*)&sa_dup[16 + kq + 2][2 * row] = make_float2(ra1.z, ra1.z);
            *(float2*)&sa_dup[16 + kq + 3][2 * row] = make_float2(ra1.w, ra1.w);
            sb[kq + 0][row] = rb0.x; sb[kq + 1][row] = rb0.y;
            sb[kq + 2][row] = rb0.z; sb[kq + 3][row] = rb0.w;
            sb[16 + kq + 0][row] = rb1.x; sb[16 + kq + 1][row] = rb1.y;
            sb[16 + kq + 2][row] = rb1.z; sb[16 + kq + 3][row] = rb1.w;
            __syncthreads();

            if (kc + 32 < H_) {
                const int kn = kc + 32;
                ra0 = *(const float4*)&s[(b0 + row) * H_ + kn + kq];
                ra1 = *(const float4*)&s[(b0 + row) * H_ + kn + 16 + kq];
                if (!gate_tile) {
                    rb0 = *(const float4*)&W[(m0 + row) * H_ + kn + kq];
                    rb1 = *(const float4*)&W[(m0 + row) * H_ + kn + 16 + kq];
                } else {
                    float4 x0 = *(const float4*)&h[row * H_ + kn + kq];
                    float4 x1 = *(const float4*)&h[row * H_ + kn + 16 + kq];
                    float4 y0 = *(const float4*)&w[row * H_ + kn + kq];
                    float4 y1 = *(const float4*)&w[row * H_ + kn + 16 + kq];
                    rb0 = make_float4(x0.x + y0.x, x0.y + y0.y, x0.z + y0.z, x0.w + y0.w);
                    rb1 = make_float4(x1.x + y1.x, x1.y + y1.y, x1.z + y1.z, x1.w + y1.w);
                }
            }

#pragma unroll 8
            for (int k = 0; k < 32; ++k) {
                const ulonglong2 ad01 = *(const ulonglong2*)&sa_dup[k][2 * rb];
                const ulonglong2 ad23 = *(const ulonglong2*)&sa_dup[k][2 * rb + 4];
                const ulonglong2 bp = *(const ulonglong2*)&sb[k][cm];
                acc2[0][0] = fma2(ad01.x, bp.x, acc2[0][0]);
                acc2[0][1] = fma2(ad01.x, bp.y, acc2[0][1]);
                acc2[1][0] = fma2(ad01.y, bp.x, acc2[1][0]);
                acc2[1][1] = fma2(ad01.y, bp.y, acc2[1][1]);
                acc2[2][0] = fma2(ad23.x, bp.x, acc2[2][0]);
                acc2[2][1] = fma2(ad23.x, bp.y, acc2[2][1]);
                acc2[3][0] = fma2(ad23.y, bp.x, acc2[3][0]);
                acc2[3][1] = fma2(ad23.y, bp.y, acc2[3][1]);
            }
            __syncthreads();
        }

#pragma unroll
        for (int bi = 0; bi < 4; ++bi) {
            float2 p0 = unpack2(acc2[bi][0]);
            float2 p1 = unpack2(acc2[bi][1]);
            const int b = b0 + rb + bi;
            if (!gate_tile) {
                *(float4*)&g_sW[b * H_ + m0 + cm] = make_float4(p0.x, p0.y, p1.x, p1.y);
            } else {
                *(float4*)&g_gate[b * N_ + cm] = make_float4(
                    1.0f / (1.0f + __expf(-p0.x)), 1.0f / (1.0f + __expf(-p0.y)),
                    1.0f / (1.0f + __expf(-p1.x)), 1.0f / (1.0f + __expf(-p1.y)));
            }
        }
    } else {
        // ---------------- UV part: warp per output element ----------------
        const int id = blk - 320;
        const int n = id >> 5;
        const int kg = id & 31;
        const int warp = tid >> 5;
        const int lane = tid & 31;
        const int k = kg * 8 + warp;
        const int off = lane * 8;

        const float4* u4 = (const float4*)(U + k * H_ + off);
        const float4* v4 = (const float4*)(V + k * H_ + off);
        const float4* h4 = (const float4*)(h + n * H_ + off);
        const float4* w4 = (const float4*)(w + n * H_ + off);
        float4 u0 = u4[0], u1 = u4[1];
        float4 v0 = v4[0], v1 = v4[1];
        float4 x0 = __ldg(h4), x1 = __ldg(h4 + 1);
        float4 y0 = __ldg(w4), y1 = __ldg(w4 + 1);

        float acc = 0.f;
        acc = fmaf(u0.x, x0.x, acc); acc = fmaf(u0.y, x0.y, acc);
        acc = fmaf(u0.z, x0.z, acc); acc = fmaf(u0.w, x0.w, acc);
        acc = fmaf(u1.x, x1.x, acc); acc = fmaf(u1.y, x1.y, acc);
        acc = fmaf(u1.z, x1.z, acc); acc = fmaf(u1.w, x1.w, acc);
        acc = fmaf(v0.x, y0.x, acc); acc = fmaf(v0.y, y0.y, acc);
        acc = fmaf(v0.z, y0.z, acc); acc = fmaf(v0.w, y0.w, acc);
        acc = fmaf(v1.x, y1.x, acc); acc = fmaf(v1.y, y1.y, acc);
        acc = fmaf(v1.z, y1.z, acc); acc = fmaf(v1.w, y1.w, acc);

#pragma unroll
        for (int offm = 16; offm > 0; offm >>= 1)
            acc += __shfl_xor_sync(0xFFFFFFFFu, acc, offm);
        if (lane == 0) g_UV[n * H_ + k] = acc;
    }
}

// ---------------------------------------------------------------------------
// Kernel 3 (R2 body, best measured): one warp per (b,n) row pair; sW+gate
// staged in smem, double-buffered prefetch; 16 rows per block.
// grid = (4 n-tiles, B/TB3), block = 256
// ---------------------------------------------------------------------------
__device__ __forceinline__ void row_step(const float4 uv, const float4 hh,
                                         const float4 sw, const float g,
                                         const float a, float4& o, float& ss)
{
    float c, t;
    c = uv.x + sw.x; c = (c >= 0.f) ? c : a * c; t = fmaf(g, c, hh.x); o.x = t; ss = fmaf(t, t, ss);
    c = uv.y + sw.y; c = (c >= 0.f) ? c : a * c; t = fmaf(g, c, hh.y); o.y = t; ss = fmaf(t, t, ss);
    c = uv.z + sw.z; c = (c >= 0.f) ? c : a * c; t = fmaf(g, c, hh.z); o.z = t; ss = fmaf(t, t, ss);
    c = uv.w + sw.w; c = (c >= 0.f) ? c : a * c; t = fmaf(g, c, hh.w); o.w = t; ss = fmaf(t, t, ss);
}

__global__ void __launch_bounds__(256) k3_main(
    const float* __restrict__ h, const float* __restrict__ a_ptr,
    float* __restrict__ out)
{
    __shared__ float4 sw[2][64];
    __shared__ float gt[2][16];

    const int tid = threadIdx.x;
    const int warp = tid >> 5;
    const int lane = tid & 31;
    const int n0 = blockIdx.x * 16;
    const int b0 = blockIdx.y * TB3;
    const float a = __ldg(a_ptr);

    const int nA = n0 + warp;
    const int nB = n0 + warp + 8;
    const int k0 = lane * 4;
    const int k1 = 128 + lane * 4;

    float4 uvA0 = *(const float4*)&g_UV[nA * H_ + k0];
    float4 uvA1 = *(const float4*)&g_UV[nA * H_ + k1];
    float4 uvB0 = *(const float4*)&g_UV[nB * H_ + k0];
    float4 uvB1 = *(const float4*)&g_UV[nB * H_ + k1];
    float4 hA0 = __ldg((const float4*)&h[nA * H_ + k0]);
    float4 hA1 = __ldg((const float4*)&h[nA * H_ + k1]);
    float4 hB0 = __ldg((const float4*)&h[nB * H_ + k0]);
    float4 hB1 = __ldg((const float4*)&h[nB * H_ + k1]);

    if (tid < 64) sw[0][tid] = __ldg((const float4*)&g_sW[(size_t)b0 * H_] + tid);
    else if (tid < 80) gt[0][tid - 64] = __ldg(&g_gate[b0 * N_ + n0 + (tid - 64)]);
    __syncthreads();

    for (int i = 0; i < TB3; ++i) {
        const int buf = i & 1;
        if (i + 1 < TB3) {
            const int bn = b0 + i + 1;
            if (tid < 64) sw[buf ^ 1][tid] = __ldg((const float4*)&g_sW[(size_t)bn * H_] + tid);
            else if (tid < 80) gt[buf ^ 1][tid - 64] = __ldg(&g_gate[bn * N_ + n0 + (tid - 64)]);
        }

        const float4 s0 = sw[buf][lane];
        const float4 s1 = sw[buf][lane + 32];
        const float gA = gt[buf][warp];
        const float gB = gt[buf][warp + 8];

        float4 oA0, oA1, oB0, oB1;
        float ssA = 0.f, ssB = 0.f;
        row_step(uvA0, hA0, s0, gA, a, oA0, ssA);
        row_step(uvA1, hA1, s1, gA, a, oA1, ssA);
        row_step(uvB0, hB0, s0, gB, a, oB0, ssB);
        row_step(uvB1, hB1, s1, gB, a, oB1, ssB);

#pragma unroll
        for (int offm = 16; offm > 0; offm >>= 1) {
            ssA += __shfl_xor_sync(0xFFFFFFFFu, ssA, offm);
            ssB += __shfl_xor_sync(0xFFFFFFFFu, ssB, offm);
        }
        const float iA = rsqrtf(ssA);
        const float iB = rsqrtf(ssB);

        const int b = b0 + i;
        float4* oA = (float4*)&out[((size_t)b * N_ + nA) * H_];
        float4* oB = (float4*)&out[((size_t)b * N_ + nB) * H_];
        oA[lane]      = make_float4(oA0.x * iA, oA0.y * iA, oA0.z * iA, oA0.w * iA);
        oA[32 + lane] = make_float4(oA1.x * iA, oA1.y * iA, oA1.z * iA, oA1.w * iA);
        oB[lane]      = make_float4(oB0.x * iB, oB0.y * iB, oB0.z * iB, oB0.w * iB);
        oB[32 + lane] = make_float4(oB1.x * iB, oB1.y * iB, oB1.z * iB, oB1.w * iB);

        __syncthreads();
    }
}

// ---------------------------------------------------------------------------
extern "C" void kernel_launch(void* const* d_in, const int* in_sizes, int n_in,
                              void* d_out, int out_size)
{
    const float* s_t = (const float*)d_in[0];   // [B,H]
    const float* h   = (const float*)d_in[1];   // [1,N,H]
    const float* w   = (const float*)d_in[2];   // [1,N,H]
    const float* U   = (const float*)d_in[3];   // [H,H]
    const float* V   = (const float*)d_in[4];   // [H,H]
    const float* W   = (const float*)d_in[5];   // [H,H]
    const float* pa  = (const float*)d_in[6];   // [1]
    float* out = (float*)d_out;                 // [B,N,H]

    k12<<<320 + 2048, 256>>>(s_t, W, h, w, U, V);

    dim3 g3(N_ / 16, B_ / TB3);
    k3_main<<<g3, 256>>>(h, pa, out);
}

// round 6
// speedup vs baseline: 1.5338x; 1.0715x over previous
#include <cuda_runtime.h>

#define B_ 4096
#define N_ 64
#define H_ 256
#define TB3 32

#define NB_GEMM 160   // 32 b-tiles x 5 m-tiles (128x64 tiles)
#define NB_UV   2048

typedef unsigned long long u64;

// Scratch (allocation-free rule: __device__ globals)
__device__ float g_UV[N_ * H_];     //  64 KiB
__device__ float g_sW[B_ * H_];     //   4 MiB
__device__ float g_gate[B_ * N_];   //   1 MiB

// ---------- packed fp32x2 helpers (sm_103a FFMA2) ----------
__device__ __forceinline__ u64 pack2(float x, float y) {
    u64 r; asm("mov.b64 %0, {%1, %2};" : "=l"(r) : "f"(x), "f"(y)); return r;
}
__device__ __forceinline__ u64 fma2(u64 a, u64 b, u64 c) {
    u64 d; asm("fma.rn.f32x2 %0, %1, %2, %3;" : "=l"(d) : "l"(a), "l"(b), "l"(c)); return d;
}
__device__ __forceinline__ float2 unpack2(u64 v) {
    float2 r; asm("mov.b64 {%0, %1}, %2;" : "=f"(r.x), "=f"(r.y) : "l"(v)); return r;
}

// ---------------------------------------------------------------------------
// Merged kernel 1+2:
//  blocks [0,160):   GEMM  C[b,m] = s_t[b,:].M[m,:], M = concat(W_w, h+w)
//    128b x 64m tile, Kc=32, k-major smem (conflict-free scalar staging),
//    8b x 4m micro per thread via f32x2 packed FMA (16 FFMA2 / k).
//    m<256 -> g_sW ; gate tile (mx==4) -> g_gate = sigmoid(C)
//  blocks [160, 2208): UV[n,k] = sum_h h[n,h]*U[k,h] + w[n,h]*V[k,h]
// ---------------------------------------------------------------------------
__global__ void __launch_bounds__(256) k12(
    const float* __restrict__ s, const float* __restrict__ W,
    const float* __restrict__ h, const float* __restrict__ w,
    const float* __restrict__ U, const float* __restrict__ V)
{
    __shared__ float sa[32][128];  // [k][b_local] 16 KiB
    __shared__ float sb[32][64];   // [k][m_local]  8 KiB

    const int tid = threadIdx.x;
    const int blk = blockIdx.x;

    if (blk < NB_GEMM) {
        const int mx = blk % 5;
        const int b0 = (blk / 5) * 128;
        const int m0 = mx * 64;
        const bool gate_tile = (mx == 4);

        // staging thread mapping
        const int arow = tid & 127;          // A row (128 rows)
        const int akh = (tid >> 7) * 16;     // A k half: 0 or 16
        const int brow = tid & 63;           // B row (64 rows)
        const int bkq = (tid >> 6) * 8;      // B k quarter: 0,8,16,24

        // compute thread mapping: 8b x 4m micro
        const int ty = tid >> 4;             // 0..15 -> b base ty*8
        const int tx = tid & 15;             // 0..15 -> m base tx*4
        const int rb = ty << 3;
        const int cm = tx << 2;

        u64 acc2[4][4] = {};                 // [b-pair][m]

        float4 ra[4], rbv[2];
        // prologue loads (kc = 0)
#pragma unroll
        for (int q = 0; q < 4; ++q)
            ra[q] = *(const float4*)&s[(b0 + arow) * H_ + akh + 4 * q];
        if (!gate_tile) {
#pragma unroll
            for (int q = 0; q < 2; ++q)
                rbv[q] = *(const float4*)&W[(m0 + brow) * H_ + bkq + 4 * q];
        } else {
#pragma unroll
            for (int q = 0; q < 2; ++q) {
                float4 x = *(const float4*)&h[brow * H_ + bkq + 4 * q];
                float4 y = *(const float4*)&w[brow * H_ + bkq + 4 * q];
                rbv[q] = make_float4(x.x + y.x, x.y + y.y, x.z + y.z, x.w + y.w);
            }
        }

        for (int kc = 0; kc < H_; kc += 32) {
            // conflict-free scalar staging (consecutive lanes -> consecutive banks)
#pragma unroll
            for (int q = 0; q < 4; ++q) {
                sa[akh + 4 * q + 0][arow] = ra[q].x;
                sa[akh + 4 * q + 1][arow] = ra[q].y;
                sa[akh + 4 * q + 2][arow] = ra[q].z;
                sa[akh + 4 * q + 3][arow] = ra[q].w;
            }
#pragma unroll
            for (int q = 0; q < 2; ++q) {
                sb[bkq + 4 * q + 0][brow] = rbv[q].x;
                sb[bkq + 4 * q + 1][brow] = rbv[q].y;
                sb[bkq + 4 * q + 2][brow] = rbv[q].z;
                sb[bkq + 4 * q + 3][brow] = rbv[q].w;
            }
            __syncthreads();

            // prefetch next chunk
            if (kc + 32 < H_) {
                const int kn = kc + 32;
#pragma unroll
                for (int q = 0; q < 4; ++q)
                    ra[q] = *(const float4*)&s[(b0 + arow) * H_ + kn + akh + 4 * q];
                if (!gate_tile) {
#pragma unroll
                    for (int q = 0; q < 2; ++q)
                        rbv[q] = *(const float4*)&W[(m0 + brow) * H_ + kn + bkq + 4 * q];
                } else {
#pragma unroll
                    for (int q = 0; q < 2; ++q) {
                        float4 x = *(const float4*)&h[brow * H_ + kn + bkq + 4 * q];
                        float4 y = *(const float4*)&w[brow * H_ + kn + bkq + 4 * q];
                        rbv[q] = make_float4(x.x + y.x, x.y + y.y, x.z + y.z, x.w + y.w);
                    }
                }
            }

#pragma unroll 8
            for (int k = 0; k < 32; ++k) {
                const ulonglong2 a01 = *(const ulonglong2*)&sa[k][rb];      // rows rb..rb+3
                const ulonglong2 a23 = *(const ulonglong2*)&sa[k][rb + 4];  // rows rb+4..rb+7
                const float4 bv = *(const float4*)&sb[k][cm];
                const u64 bx = pack2(bv.x, bv.x);
                const u64 by = pack2(bv.y, bv.y);
                const u64 bz = pack2(bv.z, bv.z);
                const u64 bw = pack2(bv.w, bv.w);
                acc2[0][0] = fma2(a01.x, bx, acc2[0][0]);
                acc2[0][1] = fma2(a01.x, by, acc2[0][1]);
                acc2[0][2] = fma2(a01.x, bz, acc2[0][2]);
                acc2[0][3] = fma2(a01.x, bw, acc2[0][3]);
                acc2[1][0] = fma2(a01.y, bx, acc2[1][0]);
                acc2[1][1] = fma2(a01.y, by, acc2[1][1]);
                acc2[1][2] = fma2(a01.y, bz, acc2[1][2]);
                acc2[1][3] = fma2(a01.y, bw, acc2[1][3]);
                acc2[2][0] = fma2(a23.x, bx, acc2[2][0]);
                acc2[2][1] = fma2(a23.x, by, acc2[2][1]);
                acc2[2][2] = fma2(a23.x, bz, acc2[2][2]);
                acc2[2][3] = fma2(a23.x, bw, acc2[2][3]);
                acc2[3][0] = fma2(a23.y, bx, acc2[3][0]);
                acc2[3][1] = fma2(a23.y, by, acc2[3][1]);
                acc2[3][2] = fma2(a23.y, bz, acc2[3][2]);
                acc2[3][3] = fma2(a23.y, bw, acc2[3][3]);
            }
            __syncthreads();
        }

        // epilogue: acc2[p][j] -> rows b0+rb+2p(+1), col m0+cm+j
#pragma unroll
        for (int p = 0; p < 4; ++p) {
            float2 c0 = unpack2(acc2[p][0]);
            float2 c1 = unpack2(acc2[p][1]);
            float2 c2 = unpack2(acc2[p][2]);
            float2 c3 = unpack2(acc2[p][3]);
            const int b = b0 + rb + 2 * p;
            if (!gate_tile) {
                *(float4*)&g_sW[b * H_ + m0 + cm] = make_float4(c0.x, c1.x, c2.x, c3.x);
                *(float4*)&g_sW[(b + 1) * H_ + m0 + cm] = make_float4(c0.y, c1.y, c2.y, c3.y);
            } else {
                *(float4*)&g_gate[b * N_ + cm] = make_float4(
                    1.0f / (1.0f + __expf(-c0.x)), 1.0f / (1.0f + __expf(-c1.x)),
                    1.0f / (1.0f + __expf(-c2.x)), 1.0f / (1.0f + __expf(-c3.x)));
                *(float4*)&g_gate[(b + 1) * N_ + cm] = make_float4(
                    1.0f / (1.0f + __expf(-c0.y)), 1.0f / (1.0f + __expf(-c1.y)),
                    1.0f / (1.0f + __expf(-c2.y)), 1.0f / (1.0f + __expf(-c3.y)));
            }
        }
    } else {
        // ---------------- UV part: warp per output element ----------------
        const int id = blk - NB_GEMM;
        const int n = id >> 5;
        const int kg = id & 31;
        const int warp = tid >> 5;
        const int lane = tid & 31;
        const int k = kg * 8 + warp;
        const int off = lane * 8;

        const float4* u4 = (const float4*)(U + k * H_ + off);
        const float4* v4 = (const float4*)(V + k * H_ + off);
        const float4* h4 = (const float4*)(h + n * H_ + off);
        const float4* w4 = (const float4*)(w + n * H_ + off);
        float4 u0 = u4[0], u1 = u4[1];
        float4 v0 = v4[0], v1 = v4[1];
        float4 x0 = __ldg(h4), x1 = __ldg(h4 + 1);
        float4 y0 = __ldg(w4), y1 = __ldg(w4 + 1);

        float acc = 0.f;
        acc = fmaf(u0.x, x0.x, acc); acc = fmaf(u0.y, x0.y, acc);
        acc = fmaf(u0.z, x0.z, acc); acc = fmaf(u0.w, x0.w, acc);
        acc = fmaf(u1.x, x1.x, acc); acc = fmaf(u1.y, x1.y, acc);
        acc = fmaf(u1.z, x1.z, acc); acc = fmaf(u1.w, x1.w, acc);
        acc = fmaf(v0.x, y0.x, acc); acc = fmaf(v0.y, y0.y, acc);
        acc = fmaf(v0.z, y0.z, acc); acc = fmaf(v0.w, y0.w, acc);
        acc = fmaf(v1.x, y1.x, acc); acc = fmaf(v1.y, y1.y, acc);
        acc = fmaf(v1.z, y1.z, acc); acc = fmaf(v1.w, y1.w, acc);

#pragma unroll
        for (int offm = 16; offm > 0; offm >>= 1)
            acc += __shfl_xor_sync(0xFFFFFFFFu, acc, offm);
        if (lane == 0) g_UV[n * H_ + k] = acc;
    }
}

// ---------------------------------------------------------------------------
// Kernel 3 (R2 body, TB3=32 -> 512 blocks = single wave at 4 blocks/SM):
// one warp per (b,n) row pair; sW+gate staged in smem, double-buffered.
// grid = (4 n-tiles, 128 b-tiles), block = 256
// ---------------------------------------------------------------------------
__device__ __forceinline__ void row_step(const float4 uv, const float4 hh,
                                         const float4 sw, const float g,
                                         const float a, float4& o, float& ss)
{
    float c, t;
    c = uv.x + sw.x; c = (c >= 0.f) ? c : a * c; t = fmaf(g, c, hh.x); o.x = t; ss = fmaf(t, t, ss);
    c = uv.y + sw.y; c = (c >= 0.f) ? c : a * c; t = fmaf(g, c, hh.y); o.y = t; ss = fmaf(t, t, ss);
    c = uv.z + sw.z; c = (c >= 0.f) ? c : a * c; t = fmaf(g, c, hh.z); o.z = t; ss = fmaf(t, t, ss);
    c = uv.w + sw.w; c = (c >= 0.f) ? c : a * c; t = fmaf(g, c, hh.w); o.w = t; ss = fmaf(t, t, ss);
}

__global__ void __launch_bounds__(256) k3_main(
    const float* __restrict__ h, const float* __restrict__ a_ptr,
    float* __restrict__ out)
{
    __shared__ float4 sw[2][64];
    __shared__ float gt[2][16];

    const int tid = threadIdx.x;
    const int warp = tid >> 5;
    const int lane = tid & 31;
    const int n0 = blockIdx.x * 16;
    const int b0 = blockIdx.y * TB3;
    const float a = __ldg(a_ptr);

    const int nA = n0 + warp;
    const int nB = n0 + warp + 8;
    const int k0 = lane * 4;
    const int k1 = 128 + lane * 4;

    float4 uvA0 = *(const float4*)&g_UV[nA * H_ + k0];
    float4 uvA1 = *(const float4*)&g_UV[nA * H_ + k1];
    float4 uvB0 = *(const float4*)&g_UV[nB * H_ + k0];
    float4 uvB1 = *(const float4*)&g_UV[nB * H_ + k1];
    float4 hA0 = __ldg((const float4*)&h[nA * H_ + k0]);
    float4 hA1 = __ldg((const float4*)&h[nA * H_ + k1]);
    float4 hB0 = __ldg((const float4*)&h[nB * H_ + k0]);
    float4 hB1 = __ldg((const float4*)&h[nB * H_ + k1]);

    if (tid < 64) sw[0][tid] = __ldg((const float4*)&g_sW[(size_t)b0 * H_] + tid);
    else if (tid < 80) gt[0][tid - 64] = __ldg(&g_gate[b0 * N_ + n0 + (tid - 64)]);
    __syncthreads();

    for (int i = 0; i < TB3; ++i) {
        const int buf = i & 1;
        if (i + 1 < TB3) {
            const int bn = b0 + i + 1;
            if (tid < 64) sw[buf ^ 1][tid] = __ldg((const float4*)&g_sW[(size_t)bn * H_] + tid);
            else if (tid < 80) gt[buf ^ 1][tid - 64] = __ldg(&g_gate[bn * N_ + n0 + (tid - 64)]);
        }

        const float4 s0 = sw[buf][lane];
        const float4 s1 = sw[buf][lane + 32];
        const float gA = gt[buf][warp];
        const float gB = gt[buf][warp + 8];

        float4 oA0, oA1, oB0, oB1;
        float ssA = 0.f, ssB = 0.f;
        row_step(uvA0, hA0, s0, gA, a, oA0, ssA);
        row_step(uvA1, hA1, s1, gA, a, oA1, ssA);
        row_step(uvB0, hB0, s0, gB, a, oB0, ssB);
        row_step(uvB1, hB1, s1, gB, a, oB1, ssB);

#pragma unroll
        for (int offm = 16; offm > 0; offm >>= 1) {
            ssA += __shfl_xor_sync(0xFFFFFFFFu, ssA, offm);
            ssB += __shfl_xor_sync(0xFFFFFFFFu, ssB, offm);
        }
        const float iA = rsqrtf(ssA);
        const float iB = rsqrtf(ssB);

        const int b = b0 + i;
        float4* oA = (float4*)&out[((size_t)b * N_ + nA) * H_];
        float4* oB = (float4*)&out[((size_t)b * N_ + nB) * H_];
        oA[lane]      = make_float4(oA0.x * iA, oA0.y * iA, oA0.z * iA, oA0.w * iA);
        oA[32 + lane] = make_float4(oA1.x * iA, oA1.y * iA, oA1.z * iA, oA1.w * iA);
        oB[lane]      = make_float4(oB0.x * iB, oB0.y * iB, oB0.z * iB, oB0.w * iB);
        oB[32 + lane] = make_float4(oB1.x * iB, oB1.y * iB, oB1.z * iB, oB1.w * iB);

        __syncthreads();
    }
}

// ---------------------------------------------------------------------------
extern "C" void kernel_launch(void* const* d_in, const int* in_sizes, int n_in,
                              void* d_out, int out_size)
{
    const float* s_t = (const float*)d_in[0];   // [B,H]
    const float* h   = (const float*)d_in[1];   // [1,N,H]
    const float* w   = (const float*)d_in[2];   // [1,N,H]
    const float* U   = (const float*)d_in[3];   // [H,H]
    const float* V   = (const float*)d_in[4];   // [H,H]
    const float* W   = (const float*)d_in[5];   // [H,H]
    const float* pa  = (const float*)d_in[6];   // [1]
    float* out = (float*)d_out;                 // [B,N,H]

    k12<<<NB_GEMM + NB_UV, 256>>>(s_t, W, h, w, U, V);

    dim3 g3(N_ / 16, B_ / TB3);
    k3_main<<<g3, 256>>>(h, pa, out);
}